// round 3
// baseline (speedup 1.0000x reference)
#include <cuda_runtime.h>

#define BB 4
#define CC 256
#define HH 256
#define WW 256
#define HWSZ (HH * WW)
#define NPIX (BB * HWSZ)

// Per-pixel precomputed maps (channel-independent).
// g_info bits: 0 = gt class (0/1), 1 = correct (pred==gt), 2 = edge
__device__ unsigned char g_info[NPIX];
// g_msecnt: 0 if pixel not mse-masked, else cnt_corr (1..24)
__device__ unsigned char g_msecnt[NPIX];
__device__ double g_loss[2];
__device__ int g_nsel[2];
__device__ int g_cal[2];

// ---------------- Kernel A: per-pixel info (pred, correct, edge) -----------
__global__ void kernA(const int* __restrict__ gt, const float* __restrict__ clf) {
    int p = blockIdx.x * blockDim.x + threadIdx.x;
    if (p == 0) {
        g_loss[0] = 0.0; g_loss[1] = 0.0;
        g_nsel[0] = 0; g_nsel[1] = 0;
        g_cal[0] = 0; g_cal[1] = 0;
    }
    int b = p >> 16;
    int hw = p & (HWSZ - 1);
    int h = hw >> 8;
    int w = hw & (WW - 1);
    int g = gt[p];
    float c0 = clf[(size_t)(b * 2) * HWSZ + hw];
    float c1 = clf[(size_t)(b * 2 + 1) * HWSZ + hw];
    int pred = (c1 > c0) ? 1 : 0;               // argmax ties -> index 0
    int correct = (pred == g) ? 1 : 0;
    int edge = (g == -1) ? 1 : 0;
    if (h < HH - 5) edge |= (gt[p + 5 * WW] != g) ? 1 : 0;
    if (w < WW - 5) edge |= (gt[p + 5] != g) ? 1 : 0;
    g_info[p] = (unsigned char)((g & 1) | (correct << 1) | (edge << 2));
}

// ---------------- Kernel B: ring counts, mse/cal masks, counters -----------
__global__ void kernB() {
    int p = blockIdx.x * blockDim.x + threadIdx.x;
    int hw = p & (HWSZ - 1);
    int h = hw >> 8;
    int w = hw & (WW - 1);
    unsigned info = g_info[p];
    int g = info & 1;
    int correct = (info >> 1) & 1;
    int edge = (info >> 2) & 1;
    int cntCorr = 0, cntCls = 0;
#pragma unroll
    for (int dh = -2; dh <= 2; dh++) {
#pragma unroll
        for (int dw = -2; dw <= 2; dw++) {
            if (dh == 0 && dw == 0) continue;
            int hh = h + dh, wp = w + dw;
            if ((unsigned)hh < HH && (unsigned)wp < WW) {
                unsigned qi = g_info[p + dh * WW + dw];
                int same = ((int)(qi & 1) == g) ? 1 : 0;
                cntCls += same;
                cntCorr += same & (int)((qi >> 1) & 1);
            }
        }
    }
    int mse = correct & edge & (cntCorr >= 1 ? 1 : 0);
    int cal = edge & (cntCls >= 1 ? 1 : 0);
    g_msecnt[p] = (unsigned char)(mse ? cntCorr : 0);

    unsigned bm;
    bm = __ballot_sync(0xFFFFFFFFu, mse && g == 0);
    if ((threadIdx.x & 31) == 0 && bm) atomicAdd(&g_nsel[0], __popc(bm));
    bm = __ballot_sync(0xFFFFFFFFu, mse && g == 1);
    if ((threadIdx.x & 31) == 0 && bm) atomicAdd(&g_nsel[1], __popc(bm));
    bm = __ballot_sync(0xFFFFFFFFu, cal && g == 0);
    if ((threadIdx.x & 31) == 0 && bm) atomicAdd(&g_cal[0], __popc(bm));
    bm = __ballot_sync(0xFFFFFFFFu, cal && g == 1);
    if ((threadIdx.x & 31) == 0 && bm) atomicAdd(&g_cal[1], __popc(bm));
}

// ---------------- Kernel C: main loss (separable 2-class box filter) -------
// Block (34,8) = 272 threads. Lane tx loads float2 at w = w0-2+2*tx, covering
// [w0-2, w0+65]; outputs are the 64 cols [w0, w0+63] (tx in 1..32). ty owns 4
// output rows, loads 8 rows (2-row halo each side). Out-of-image rows/cols are
// handled by CLAMPING the address and ZEROING the mask coefficient -> all 8
// loads are unconditional LDG.64 (max MLP). Channel loop is software-pipelined
// (prefetch next channel before this channel's barrier). csum double-buffered
// in dynamic smem -> single __syncthreads per channel.
#define CTX 34
#define CTY 8
#define CTHREADS (CTX * CTY)
#define NCHUNK 8
#define CHPER (CC / NCHUNK)
#define CSTRIDE 72
// csum[buf][cls][row 32][col 68 used, stride 72]
#define CS_IDX(buf, cls, row, col) ((((buf) * 2 + (cls)) * 32 + (row)) * CSTRIDE + (col))
#define CS_BYTES (2 * 2 * 32 * CSTRIDE * 4)

__global__ void __launch_bounds__(CTHREADS, 2) kernC(const float* __restrict__ x) {
    extern __shared__ float cs_s[];
    __shared__ float red0[CTHREADS], red1[CTHREADS];

    const int tx = threadIdx.x, ty = threadIdx.y;
    const int tid = ty * CTX + tx;
    const int bz = blockIdx.z;
    const int b = bz >> 3;
    const int chunk = bz & (NCHUNK - 1);
    const int h0 = blockIdx.y * 32;
    const int w0 = blockIdx.x * 64;
    const int wl = w0 - 2 + 2 * tx;          // float2 start col (even)
    const bool colOK = ((unsigned)wl < 255u); // wl in [0,254]
    const int wc = colOK ? wl : 0;
    const int cr0 = ty * 4;

    const unsigned char* infoB = g_info + (size_t)b * HWSZ;
    const unsigned char* mseB = g_msecnt + (size_t)b * HWSZ;

    // ---- per-thread constant masks & clamped row offsets ----
    float2 fc0[8], fc1[8];
    int rowoff[8];
#pragma unroll
    for (int i = 0; i < 8; i++) {
        int hr = h0 + cr0 - 2 + i;
        bool rOK = ((unsigned)hr < (unsigned)HH);
        int hc = rOK ? hr : 0;
        rowoff[i] = hc * WW + wc;
        float a0 = 0.f, a1 = 0.f, b0 = 0.f, b1 = 0.f;
        if (rOK && colOK) {
            unsigned qa = infoB[rowoff[i]];
            unsigned qb = infoB[rowoff[i] + 1];
            int ga = qa & 1, ca = (qa >> 1) & 1;
            int gb = qb & 1, cb = (qb >> 1) & 1;
            a1 = (ca & ga) ? 1.f : 0.f;
            a0 = (ca & (ga ^ 1)) ? 1.f : 0.f;
            b1 = (cb & gb) ? 1.f : 0.f;
            b0 = (cb & (gb ^ 1)) ? 1.f : 0.f;
        }
        fc0[i] = make_float2(a0, b0);
        fc1[i] = make_float2(a1, b1);
    }

    // ---- per-output-pixel constants (4 rows x 2 cols) ----
    const bool oOK = (tx >= 1) && (tx <= 32);
    float inv[4][2];
    int clsb = 0, mskb = 0;  // bit r*2+j
#pragma unroll
    for (int r = 0; r < 4; r++) {
#pragma unroll
        for (int j = 0; j < 2; j++) {
            int off = (h0 + cr0 + r) * WW + wl + j;
            unsigned char mc = oOK ? mseB[off] : (unsigned char)0;
            int cl = oOK ? (int)(infoB[off] & 1) : 0;
            inv[r][j] = 1.0f / ((float)mc + 1e-5f);
            if (mc > 0) mskb |= 1 << (r * 2 + j);
            if (cl) clsb |= 1 << (r * 2 + j);
        }
    }

    float acc0 = 0.f, acc1 = 0.f;
    const float* xb = x + ((size_t)b * CC + (size_t)chunk * CHPER) * HWSZ;

    // prologue: load channel 0
    float2 xi[8];
#pragma unroll
    for (int i = 0; i < 8; i++)
        xi[i] = __ldg((const float2*)(xb + rowoff[i]));

    for (int ch = 0; ch < CHPER; ch++) {
        // ---- prefetch next channel (unconditional addresses, guarded iter) ----
        float2 xin[8];
        const float* xn = xb + (size_t)(ch + 1 < CHPER ? ch + 1 : ch) * HWSZ;
#pragma unroll
        for (int i = 0; i < 8; i++)
            xin[i] = __ldg((const float2*)(xn + rowoff[i]));

        // ---- vertical prefix sums per class (registers) ----
        float2 P0[8], P1[8];
        float s0x = 0.f, s0y = 0.f, s1x = 0.f, s1y = 0.f;
#pragma unroll
        for (int i = 0; i < 8; i++) {
            s0x = fmaf(xi[i].x, fc0[i].x, s0x);
            s0y = fmaf(xi[i].y, fc0[i].y, s0y);
            s1x = fmaf(xi[i].x, fc1[i].x, s1x);
            s1y = fmaf(xi[i].y, fc1[i].y, s1y);
            P0[i] = make_float2(s0x, s0y);
            P1[i] = make_float2(s1x, s1y);
        }
        const int buf = ch & 1;
#pragma unroll
        for (int r = 0; r < 4; r++) {
            float c0x = P0[r + 4].x - (r ? P0[r - 1].x : 0.f);
            float c0y = P0[r + 4].y - (r ? P0[r - 1].y : 0.f);
            float c1x = P1[r + 4].x - (r ? P1[r - 1].x : 0.f);
            float c1y = P1[r + 4].y - (r ? P1[r - 1].y : 0.f);
            *(float2*)&cs_s[CS_IDX(buf, 0, cr0 + r, 2 * tx)] = make_float2(c0x, c0y);
            *(float2*)&cs_s[CS_IDX(buf, 1, cr0 + r, 2 * tx)] = make_float2(c1x, c1y);
        }
        __syncthreads();  // single barrier per channel (double-buffered csum)

        // ---- masked horizontal pass + loss accumulation ----
#pragma unroll
        for (int r = 0; r < 4; r++) {
#pragma unroll
            for (int j = 0; j < 2; j++) {
                if (mskb & (1 << (r * 2 + j))) {
                    int cl = (clsb >> (r * 2 + j)) & 1;
                    const float* row = &cs_s[CS_IDX(buf, cl, cr0 + r, 0)];
                    int c = 2 * tx + j;
                    float rs = row[c - 2] + row[c - 1] + row[c] + row[c + 1] + row[c + 2];
                    float xp = j ? xi[r + 2].y : xi[r + 2].x;
                    float d = xp - (rs - xp) * inv[r][j];  // ring = box - center
                    float dd = d * d;
                    if (cl) acc1 += dd; else acc0 += dd;
                }
            }
        }

#pragma unroll
        for (int i = 0; i < 8; i++) xi[i] = xin[i];
    }

    // ---- block reduction -> 2 double atomics per block ----
    red0[tid] = acc0;
    red1[tid] = acc1;
    __syncthreads();
    if (tid < 16) { red0[tid] += red0[tid + 256]; red1[tid] += red1[tid + 256]; }
    __syncthreads();
    for (int s = 128; s > 0; s >>= 1) {
        if (tid < s) { red0[tid] += red0[tid + s]; red1[tid] += red1[tid + s]; }
        __syncthreads();
    }
    if (tid == 0) {
        atomicAdd(&g_loss[0], (double)red0[0]);
        atomicAdd(&g_loss[1], (double)red1[0]);
    }
}

// ---------------- Kernel D: finalize ---------------------------------------
__global__ void kernD(float* out) {
    double total = 0.0;
    int ncls = 0;
#pragma unroll
    for (int c = 0; c < 2; c++) {
        bool valid = (g_cal[c] >= 1) && (g_nsel[c] >= 1);
        double denom = (double)g_nsel[c] * 256.0;
        if (denom < 1.0) denom = 1.0;
        double lc = g_loss[c] / denom;
        if (valid) { total += lc; ncls++; }
    }
    out[0] = (ncls == 0) ? 0.0f : (float)(total / (double)ncls);
}

extern "C" void kernel_launch(void* const* d_in, const int* in_sizes, int n_in,
                              void* d_out, int out_size) {
    const float* xfeat = (const float*)d_in[0];   // [4,256,256,256] f32
    const float* clf   = (const float*)d_in[1];   // [4,2,256,256]   f32
    const int*   gt    = (const int*)d_in[2];     // [4,256,256]     i32
    float* out = (float*)d_out;

    kernA<<<NPIX / 256, 256>>>(gt, clf);
    kernB<<<NPIX / 256, 256>>>();
    dim3 blk(CTX, CTY);
    dim3 grd(WW / 64, HH / 32, BB * NCHUNK);  // 4 x 8 x 32 = 1024 blocks
    kernC<<<grd, blk, CS_BYTES>>>(xfeat);     // <-- dynamic smem now passed
    kernD<<<1, 1>>>(out);
}